// round 1
// baseline (speedup 1.0000x reference)
#include <cuda_runtime.h>

// Problem constants
#define BBATCH 4
#define NROW   2048
#define CDIM   256
#define ICDIM  128
#define MTOT   (BBATCH*NROW)       // 8192 rows total (batch folded)
#define PER_B  (NROW*CDIM)         // 524288 floats per batch
#define TWO_N  4096                // 2*N, the flattened inner length
#define SPLIT  32
#define KCH    (TWO_N/SPLIT)       // 128

// Scratch (static device globals; no allocation allowed)
__device__ float g_Xg[MTOT*CDIM];      // detect @ g
__device__ float g_Xphi[MTOT*CDIM];    // detect @ phi
__device__ float g_Xg2[MTOT*CDIM];     // aim @ g2
__device__ float g_Xtheta[MTOT*CDIM];  // aim @ theta
__device__ float g_part[BBATCH*2*SPLIT*ICDIM*ICDIM];  // split-K partials
__device__ float g_Ms[BBATCH*2*ICDIM*ICDIM];          // scaled 128x128 matrices
__device__ float g_Tdet[MTOT*CDIM];
__device__ float g_Taim[MTOT*CDIM];

// ---------------------------------------------------------------------------
// Linear: Y[m,n] = sum_k X[m,k]*W[n,k] + b[n]   (M=8192, N=256, K=256)
// BM=128, BN=64, BK=16; 256 threads; 8x4 micro-tile.
// dstSel: 0=g_Xg 1=g_Xphi 2=g_Xg2 3=g_Xtheta
// ---------------------------------------------------------------------------
__global__ __launch_bounds__(256) void linear_k(
    const float* __restrict__ X, const float* __restrict__ W,
    const float* __restrict__ bias, int dstSel)
{
    float* __restrict__ Y =
        (dstSel == 0) ? g_Xg : (dstSel == 1) ? g_Xphi : (dstSel == 2) ? g_Xg2 : g_Xtheta;

    __shared__ float Xs[16][128];
    __shared__ float Ws[16][64];
    const int t = threadIdx.x;
    const int ty = t >> 4, tx = t & 15;
    const int m0 = blockIdx.x * 128, n0 = blockIdx.y * 64;

    float acc[8][4];
#pragma unroll
    for (int i = 0; i < 8; i++)
#pragma unroll
        for (int j = 0; j < 4; j++) acc[i][j] = 0.f;

    for (int k0 = 0; k0 < CDIM; k0 += 16) {
#pragma unroll
        for (int l = 0; l < 2; l++) {
            int id = t + l * 256;                 // 0..511
            int row = id >> 2, kq = (id & 3) << 2;
            float4 v = *(const float4*)(X + (size_t)(m0 + row) * CDIM + k0 + kq);
            Xs[kq + 0][row] = v.x; Xs[kq + 1][row] = v.y;
            Xs[kq + 2][row] = v.z; Xs[kq + 3][row] = v.w;
        }
        {
            int row = t >> 2, kq = (t & 3) << 2;
            float4 v = *(const float4*)(W + (size_t)(n0 + row) * CDIM + k0 + kq);
            Ws[kq + 0][row] = v.x; Ws[kq + 1][row] = v.y;
            Ws[kq + 2][row] = v.z; Ws[kq + 3][row] = v.w;
        }
        __syncthreads();
#pragma unroll
        for (int kk = 0; kk < 16; kk++) {
            float a[8], w[4];
#pragma unroll
            for (int i = 0; i < 8; i++) a[i] = Xs[kk][ty * 8 + i];
#pragma unroll
            for (int j = 0; j < 4; j++) w[j] = Ws[kk][tx * 4 + j];
#pragma unroll
            for (int i = 0; i < 8; i++)
#pragma unroll
                for (int j = 0; j < 4; j++) acc[i][j] = fmaf(a[i], w[j], acc[i][j]);
        }
        __syncthreads();
    }
#pragma unroll
    for (int i = 0; i < 8; i++) {
        int m = m0 + ty * 8 + i;
#pragma unroll
        for (int j = 0; j < 4; j++) {
            int n = n0 + tx * 4 + j;
            Y[(size_t)m * CDIM + n] = acc[i][j] + bias[n];
        }
    }
}

// ---------------------------------------------------------------------------
// Final linear with bias + residual, writes straight into d_out.
// srcSel: 0 = g_Tdet, 1 = g_Taim
// ---------------------------------------------------------------------------
__global__ __launch_bounds__(256) void linear_res_k(
    int srcSel, const float* __restrict__ W, const float* __restrict__ bias,
    const float* __restrict__ res, float* __restrict__ Y)
{
    const float* __restrict__ X = srcSel ? g_Taim : g_Tdet;

    __shared__ float Xs[16][128];
    __shared__ float Ws[16][64];
    const int t = threadIdx.x;
    const int ty = t >> 4, tx = t & 15;
    const int m0 = blockIdx.x * 128, n0 = blockIdx.y * 64;

    float acc[8][4];
#pragma unroll
    for (int i = 0; i < 8; i++)
#pragma unroll
        for (int j = 0; j < 4; j++) acc[i][j] = 0.f;

    for (int k0 = 0; k0 < CDIM; k0 += 16) {
#pragma unroll
        for (int l = 0; l < 2; l++) {
            int id = t + l * 256;
            int row = id >> 2, kq = (id & 3) << 2;
            float4 v = *(const float4*)(X + (size_t)(m0 + row) * CDIM + k0 + kq);
            Xs[kq + 0][row] = v.x; Xs[kq + 1][row] = v.y;
            Xs[kq + 2][row] = v.z; Xs[kq + 3][row] = v.w;
        }
        {
            int row = t >> 2, kq = (t & 3) << 2;
            float4 v = *(const float4*)(W + (size_t)(n0 + row) * CDIM + k0 + kq);
            Ws[kq + 0][row] = v.x; Ws[kq + 1][row] = v.y;
            Ws[kq + 2][row] = v.z; Ws[kq + 3][row] = v.w;
        }
        __syncthreads();
#pragma unroll
        for (int kk = 0; kk < 16; kk++) {
            float a[8], w[4];
#pragma unroll
            for (int i = 0; i < 8; i++) a[i] = Xs[kk][ty * 8 + i];
#pragma unroll
            for (int j = 0; j < 4; j++) w[j] = Ws[kk][tx * 4 + j];
#pragma unroll
            for (int i = 0; i < 8; i++)
#pragma unroll
                for (int j = 0; j < 4; j++) acc[i][j] = fmaf(a[i], w[j], acc[i][j]);
        }
        __syncthreads();
    }
#pragma unroll
    for (int i = 0; i < 8; i++) {
        int m = m0 + ty * 8 + i;
#pragma unroll
        for (int j = 0; j < 4; j++) {
            int n = n0 + tx * 4 + j;
            Y[(size_t)m * CDIM + n] = acc[i][j] + bias[n] + res[(size_t)m * CDIM + n];
        }
    }
}

// ---------------------------------------------------------------------------
// Pairdot: the two [128x128] inner matrices, split-K over TWO_N=4096.
//   which=0: M1[i,j] = sum_m Xphi_flat[i*4096+m] * Xg_flat[j*4096+m]
//   which=1: M2[i,j] = sum_m Xtheta_flat[i*4096+m] * Xg2_flat[j*4096+m]
// grid (SPLIT, 2, B); 256 threads; 8x8 micro-tile; partials to g_part.
// ---------------------------------------------------------------------------
__global__ __launch_bounds__(256) void pairdot_k()
{
    const int s = blockIdx.x, which = blockIdx.y, b = blockIdx.z;
    const float* __restrict__ A  = (which ? g_Xtheta : g_Xphi) + (size_t)b * PER_B;
    const float* __restrict__ Bp = (which ? g_Xg2   : g_Xg)   + (size_t)b * PER_B;
    float* __restrict__ out = g_part + (size_t)((b * 2 + which) * SPLIT + s) * (ICDIM * ICDIM);

    __shared__ float As[16][128];
    __shared__ float Bs[16][128];
    const int t = threadIdx.x, ty = t >> 4, tx = t & 15;

    float acc[8][8];
#pragma unroll
    for (int i = 0; i < 8; i++)
#pragma unroll
        for (int j = 0; j < 8; j++) acc[i][j] = 0.f;

    const int kbeg = s * KCH;
    for (int k0 = kbeg; k0 < kbeg + KCH; k0 += 16) {
#pragma unroll
        for (int l = 0; l < 2; l++) {
            int id = t + l * 256;
            int row = id >> 2, kq = (id & 3) << 2;
            float4 va = *(const float4*)(A + (size_t)row * TWO_N + k0 + kq);
            As[kq + 0][row] = va.x; As[kq + 1][row] = va.y;
            As[kq + 2][row] = va.z; As[kq + 3][row] = va.w;
            float4 vb = *(const float4*)(Bp + (size_t)row * TWO_N + k0 + kq);
            Bs[kq + 0][row] = vb.x; Bs[kq + 1][row] = vb.y;
            Bs[kq + 2][row] = vb.z; Bs[kq + 3][row] = vb.w;
        }
        __syncthreads();
#pragma unroll
        for (int kk = 0; kk < 16; kk++) {
            float a[8], w[8];
#pragma unroll
            for (int i = 0; i < 8; i++) a[i] = As[kk][ty * 8 + i];
#pragma unroll
            for (int j = 0; j < 8; j++) w[j] = Bs[kk][tx * 8 + j];
#pragma unroll
            for (int i = 0; i < 8; i++)
#pragma unroll
                for (int j = 0; j < 8; j++) acc[i][j] = fmaf(a[i], w[j], acc[i][j]);
        }
        __syncthreads();
    }
#pragma unroll
    for (int i = 0; i < 8; i++)
#pragma unroll
        for (int j = 0; j < 8; j++)
            out[(ty * 8 + i) * ICDIM + tx * 8 + j] = acc[i][j];
}

// Deterministic split-K reduce + 1/4096 scale.
__global__ void reduce_k()
{
    const int e = blockIdx.x * 256 + threadIdx.x;   // over B*2*16384 = 131072
    const int bw = e >> 14, loc = e & 16383;
    float sum = 0.f;
#pragma unroll
    for (int s = 0; s < SPLIT; s++)
        sum += g_part[(size_t)(bw * SPLIT + s) * (ICDIM * ICDIM) + loc];
    g_Ms[(size_t)bw * (ICDIM * ICDIM) + loc] = sum * (1.0f / 4096.0f);
}

// ---------------------------------------------------------------------------
// Combine: out2d[q*16+p, c] = sum_i Ms[i,q] * X[i*16+p, c]
//   which=0: src=g_Xtheta, M=M1s -> g_Taim
//   which=1: src=g_Xphi,   M=M2s -> g_Tdet
// grid (2 c-tiles, 16 p, B*2); 256 threads; 8x8 micro-tile.
// ---------------------------------------------------------------------------
__global__ __launch_bounds__(256) void combine_k()
{
    const int ct = blockIdx.x;       // c-tile: 0..1
    const int p  = blockIdx.y;       // 0..15
    const int bw = blockIdx.z;       // b*2+which
    const int b = bw >> 1, which = bw & 1;
    const float* __restrict__ src = (which ? g_Xphi : g_Xtheta) + (size_t)b * PER_B;
    const float* __restrict__ M   = g_Ms + (size_t)bw * (ICDIM * ICDIM);
    float* __restrict__ dst = (which ? g_Tdet : g_Taim) + (size_t)b * PER_B;
    const int c0 = ct * 128;

    __shared__ float Ms_s[16][128];
    __shared__ float Xs[16][128];
    const int t = threadIdx.x, ty = t >> 4, tx = t & 15;

    float acc[8][8];
#pragma unroll
    for (int i = 0; i < 8; i++)
#pragma unroll
        for (int j = 0; j < 8; j++) acc[i][j] = 0.f;

    for (int i0 = 0; i0 < ICDIM; i0 += 16) {
#pragma unroll
        for (int l = 0; l < 2; l++) {
            int id = t + l * 256;            // 0..511
            int kk = id >> 5, c4 = (id & 31) << 2;
            *(float4*)&Ms_s[kk][c4] =
                *(const float4*)(M + (size_t)(i0 + kk) * ICDIM + c4);
            *(float4*)&Xs[kk][c4] =
                *(const float4*)(src + (size_t)((i0 + kk) * 16 + p) * CDIM + c0 + c4);
        }
        __syncthreads();
#pragma unroll
        for (int kk = 0; kk < 16; kk++) {
            float a[8], x[8];
#pragma unroll
            for (int i = 0; i < 8; i++) a[i] = Ms_s[kk][ty * 8 + i];
#pragma unroll
            for (int j = 0; j < 8; j++) x[j] = Xs[kk][tx * 8 + j];
#pragma unroll
            for (int i = 0; i < 8; i++)
#pragma unroll
                for (int j = 0; j < 8; j++) acc[i][j] = fmaf(a[i], x[j], acc[i][j]);
        }
        __syncthreads();
    }
#pragma unroll
    for (int i = 0; i < 8; i++) {
        int q = ty * 8 + i;
#pragma unroll
        for (int j = 0; j < 8; j++)
            dst[(size_t)(q * 16 + p) * CDIM + c0 + tx * 8 + j] = acc[i][j];
    }
}

// ---------------------------------------------------------------------------
extern "C" void kernel_launch(void* const* d_in, const int* in_sizes, int n_in,
                              void* d_out, int out_size)
{
    const float* detect  = (const float*)d_in[0];
    const float* aim     = (const float*)d_in[1];
    const float* g_w     = (const float*)d_in[2];
    const float* g_b     = (const float*)d_in[3];
    const float* g2_w    = (const float*)d_in[4];
    const float* g2_b    = (const float*)d_in[5];
    const float* theta_w = (const float*)d_in[6];
    const float* theta_b = (const float*)d_in[7];
    const float* phi_w   = (const float*)d_in[8];
    const float* phi_b   = (const float*)d_in[9];
    const float* W_w     = (const float*)d_in[10];
    const float* W_b     = (const float*)d_in[11];
    const float* Q_w     = (const float*)d_in[12];
    const float* Q_b     = (const float*)d_in[13];

    float* out_det = (float*)d_out;                              // non_det first
    float* out_aim = (float*)d_out + (size_t)MTOT * CDIM;        // then non_aim

    dim3 gLin(MTOT / 128, CDIM / 64);   // 64 x 4
    dim3 blk(256);

    // Stage 1: the four projection linears
    linear_k<<<gLin, blk>>>(detect, g_w,     g_b,     0);  // g_Xg
    linear_k<<<gLin, blk>>>(detect, phi_w,   phi_b,   1);  // g_Xphi
    linear_k<<<gLin, blk>>>(aim,    g2_w,    g2_b,    2);  // g_Xg2
    linear_k<<<gLin, blk>>>(aim,    theta_w, theta_b, 3);  // g_Xtheta

    // Stage 2: 128x128 inner matrices via split-K + deterministic reduce
    pairdot_k<<<dim3(SPLIT, 2, BBATCH), blk>>>();
    reduce_k<<<dim3(BBATCH * 2 * ICDIM * ICDIM / 256), blk>>>();

    // Stage 3: combine back to [2048,256] tiles
    combine_k<<<dim3(2, 16, BBATCH * 2), blk>>>();

    // Stage 4: output linears with bias + residual
    linear_res_k<<<gLin, blk>>>(0, Q_w, Q_b, detect, out_det);  // non_det
    linear_res_k<<<gLin, blk>>>(1, W_w, W_b, aim,    out_aim);  // non_aim
}

// round 3
// speedup vs baseline: 1.5533x; 1.5533x over previous
#include <cuda_runtime.h>

// Problem constants
#define BBATCH 4
#define NROW   2048
#define CDIM   256
#define ICDIM  128
#define MTOT   (BBATCH*NROW)       // 8192 rows (batch folded)
#define PER_B  (NROW*CDIM)         // 524288 floats per batch
#define TWO_N  4096
#define SPLIT  32
#define KCH    (TWO_N/SPLIT)       // 128

// Scratch (static device globals; no allocation allowed)
__device__ float g_Xg[MTOT*CDIM];
__device__ float g_Xphi[MTOT*CDIM];
__device__ float g_Xg2[MTOT*CDIM];
__device__ float g_Xtheta[MTOT*CDIM];
__device__ float g_part[BBATCH*2*SPLIT*ICDIM*ICDIM];
__device__ float g_Ms[BBATCH*2*ICDIM*ICDIM];
__device__ float g_Tdet[MTOT*CDIM];
__device__ float g_Taim[MTOT*CDIM];

// ---------------------------------------------------------------------------
// Core: 128x128 tile NT-GEMM mainloop, BK=8, double-buffered, 256 threads,
// 8x8 microtile split as 4+4 quads (conflict-free float4 LDS).
// Aptr/Bptr already offset to (row, k-start); K contiguous, advance 8/iter.
// ---------------------------------------------------------------------------
__device__ __forceinline__ void gemm_nt_main(
    const float* __restrict__ Aptr, const float* __restrict__ Bptr,
    int nIter, float (&acc)[8][8],
    float (&As)[2][8][128], float (&Bs)[2][8][128],
    int lrow, int lk, int ty, int tx)
{
    float4 av = *(const float4*)Aptr;
    float4 bv = *(const float4*)Bptr;
    As[0][lk+0][lrow]=av.x; As[0][lk+1][lrow]=av.y;
    As[0][lk+2][lrow]=av.z; As[0][lk+3][lrow]=av.w;
    Bs[0][lk+0][lrow]=bv.x; Bs[0][lk+1][lrow]=bv.y;
    Bs[0][lk+2][lrow]=bv.z; Bs[0][lk+3][lrow]=bv.w;
    __syncthreads();

    for (int it = 0; it < nIter; ++it) {
        const int cur = it & 1, nxt = cur ^ 1;
        const bool has = (it + 1 < nIter);
        float4 av2, bv2;
        if (has) {
            av2 = *(const float4*)(Aptr + (size_t)(it + 1) * 8);
            bv2 = *(const float4*)(Bptr + (size_t)(it + 1) * 8);
        }
#pragma unroll
        for (int kk = 0; kk < 8; kk++) {
            float a[8], b[8];
            *(float4*)&a[0] = *(const float4*)&As[cur][kk][ty*4];
            *(float4*)&a[4] = *(const float4*)&As[cur][kk][64 + ty*4];
            *(float4*)&b[0] = *(const float4*)&Bs[cur][kk][tx*4];
            *(float4*)&b[4] = *(const float4*)&Bs[cur][kk][64 + tx*4];
#pragma unroll
            for (int i = 0; i < 8; i++)
#pragma unroll
                for (int j = 0; j < 8; j++)
                    acc[i][j] = fmaf(a[i], b[j], acc[i][j]);
        }
        if (has) {
            As[nxt][lk+0][lrow]=av2.x; As[nxt][lk+1][lrow]=av2.y;
            As[nxt][lk+2][lrow]=av2.z; As[nxt][lk+3][lrow]=av2.w;
            Bs[nxt][lk+0][lrow]=bv2.x; Bs[nxt][lk+1][lrow]=bv2.y;
            Bs[nxt][lk+2][lrow]=bv2.z; Bs[nxt][lk+3][lrow]=bv2.w;
            __syncthreads();
        }
    }
}

// ---------------------------------------------------------------------------
// Fused projection linears: z selects one of 4 (X, W, bias, dst) configs.
// grid (64, 2, 4), 256 threads.
// ---------------------------------------------------------------------------
__global__ __launch_bounds__(256) void proj_k(
    const float* __restrict__ detect, const float* __restrict__ aim,
    const float* __restrict__ g_w,     const float* __restrict__ g_b,
    const float* __restrict__ phi_w,   const float* __restrict__ phi_b,
    const float* __restrict__ g2_w,    const float* __restrict__ g2_b,
    const float* __restrict__ theta_w, const float* __restrict__ theta_b)
{
    const int z = blockIdx.z;
    const float* X; const float* W; const float* bias; float* Y;
    if (z == 0)      { X = detect; W = g_w;     bias = g_b;     Y = g_Xg; }
    else if (z == 1) { X = detect; W = phi_w;   bias = phi_b;   Y = g_Xphi; }
    else if (z == 2) { X = aim;    W = g2_w;    bias = g2_b;    Y = g_Xg2; }
    else             { X = aim;    W = theta_w; bias = theta_b; Y = g_Xtheta; }

    __shared__ float As[2][8][128];
    __shared__ float Bs[2][8][128];
    const int t = threadIdx.x;
    const int ty = (t >> 4), tx = (t & 15);
    const int lrow = t >> 1, lk = (t & 1) * 4;
    const int m0 = blockIdx.x * 128, n0 = blockIdx.y * 128;

    float acc[8][8];
#pragma unroll
    for (int i = 0; i < 8; i++)
#pragma unroll
        for (int j = 0; j < 8; j++) acc[i][j] = 0.f;

    gemm_nt_main(X + (size_t)(m0 + lrow) * CDIM + lk,
                 W + (size_t)(n0 + lrow) * CDIM + lk,
                 CDIM / 8, acc, As, Bs, lrow, lk, ty, tx);

    float b_lo[4], b_hi[4];
#pragma unroll
    for (int j = 0; j < 4; j++) {
        b_lo[j] = bias[n0 + tx*4 + j];
        b_hi[j] = bias[n0 + 64 + tx*4 + j];
    }
#pragma unroll
    for (int i = 0; i < 8; i++) {
        const int m = m0 + ((i < 4) ? (ty*4 + i) : (64 + ty*4 + i - 4));
        float4 v0, v1;
        v0.x = acc[i][0] + b_lo[0]; v0.y = acc[i][1] + b_lo[1];
        v0.z = acc[i][2] + b_lo[2]; v0.w = acc[i][3] + b_lo[3];
        v1.x = acc[i][4] + b_hi[0]; v1.y = acc[i][5] + b_hi[1];
        v1.z = acc[i][6] + b_hi[2]; v1.w = acc[i][7] + b_hi[3];
        *(float4*)(Y + (size_t)m * CDIM + n0 + tx*4)      = v0;
        *(float4*)(Y + (size_t)m * CDIM + n0 + 64 + tx*4) = v1;
    }
}

// ---------------------------------------------------------------------------
// Fused output linears with bias + residual: z=0 -> out_det, z=1 -> out_aim.
// grid (64, 2, 2).
// ---------------------------------------------------------------------------
__global__ __launch_bounds__(256) void outlin_k(
    const float* __restrict__ Q_w, const float* __restrict__ Q_b,
    const float* __restrict__ W_w, const float* __restrict__ W_b,
    const float* __restrict__ detect, const float* __restrict__ aim,
    float* __restrict__ out)
{
    const int z = blockIdx.z;
    const float* X    = z ? g_Taim : g_Tdet;
    const float* W    = z ? W_w : Q_w;
    const float* bias = z ? W_b : Q_b;
    const float* res  = z ? aim : detect;
    float* Y = out + (size_t)z * MTOT * CDIM;

    __shared__ float As[2][8][128];
    __shared__ float Bs[2][8][128];
    const int t = threadIdx.x;
    const int ty = (t >> 4), tx = (t & 15);
    const int lrow = t >> 1, lk = (t & 1) * 4;
    const int m0 = blockIdx.x * 128, n0 = blockIdx.y * 128;

    float acc[8][8];
#pragma unroll
    for (int i = 0; i < 8; i++)
#pragma unroll
        for (int j = 0; j < 8; j++) acc[i][j] = 0.f;

    gemm_nt_main(X + (size_t)(m0 + lrow) * CDIM + lk,
                 W + (size_t)(n0 + lrow) * CDIM + lk,
                 CDIM / 8, acc, As, Bs, lrow, lk, ty, tx);

    float b_lo[4], b_hi[4];
#pragma unroll
    for (int j = 0; j < 4; j++) {
        b_lo[j] = bias[n0 + tx*4 + j];
        b_hi[j] = bias[n0 + 64 + tx*4 + j];
    }
#pragma unroll
    for (int i = 0; i < 8; i++) {
        const int m = m0 + ((i < 4) ? (ty*4 + i) : (64 + ty*4 + i - 4));
        float4 r0 = *(const float4*)(res + (size_t)m * CDIM + n0 + tx*4);
        float4 r1 = *(const float4*)(res + (size_t)m * CDIM + n0 + 64 + tx*4);
        float4 v0, v1;
        v0.x = acc[i][0] + b_lo[0] + r0.x; v0.y = acc[i][1] + b_lo[1] + r0.y;
        v0.z = acc[i][2] + b_lo[2] + r0.z; v0.w = acc[i][3] + b_lo[3] + r0.w;
        v1.x = acc[i][4] + b_hi[0] + r1.x; v1.y = acc[i][5] + b_hi[1] + r1.y;
        v1.z = acc[i][6] + b_hi[2] + r1.z; v1.w = acc[i][7] + b_hi[3] + r1.w;
        *(float4*)(Y + (size_t)m * CDIM + n0 + tx*4)      = v0;
        *(float4*)(Y + (size_t)m * CDIM + n0 + 64 + tx*4) = v1;
    }
}

// ---------------------------------------------------------------------------
// Pairdot: two [128x128] inner matrices, split-K over TWO_N.
// grid (SPLIT, 2, B), one 128x128 tile per block, K=KCH.
// ---------------------------------------------------------------------------
__global__ __launch_bounds__(256) void pairdot_k()
{
    const int s = blockIdx.x, which = blockIdx.y, b = blockIdx.z;
    const float* __restrict__ A  = (which ? g_Xtheta : g_Xphi) + (size_t)b * PER_B;
    const float* __restrict__ Bp = (which ? g_Xg2   : g_Xg)    + (size_t)b * PER_B;
    float* __restrict__ out = g_part + (size_t)((b * 2 + which) * SPLIT + s) * (ICDIM * ICDIM);

    __shared__ float As[2][8][128];
    __shared__ float Bs[2][8][128];
    const int t = threadIdx.x;
    const int ty = (t >> 4), tx = (t & 15);
    const int lrow = t >> 1, lk = (t & 1) * 4;

    float acc[8][8];
#pragma unroll
    for (int i = 0; i < 8; i++)
#pragma unroll
        for (int j = 0; j < 8; j++) acc[i][j] = 0.f;

    const int kbeg = s * KCH;
    gemm_nt_main(A  + (size_t)lrow * TWO_N + kbeg + lk,
                 Bp + (size_t)lrow * TWO_N + kbeg + lk,
                 KCH / 8, acc, As, Bs, lrow, lk, ty, tx);

#pragma unroll
    for (int i = 0; i < 8; i++) {
        const int r = (i < 4) ? (ty*4 + i) : (64 + ty*4 + i - 4);
        *(float4*)(out + r * ICDIM + tx*4)      = *(float4*)&acc[i][0];
        *(float4*)(out + r * ICDIM + 64 + tx*4) = *(float4*)&acc[i][4];
    }
}

// Deterministic split-K reduce + 1/4096 scale.
__global__ void reduce_k()
{
    const int e = blockIdx.x * 256 + threadIdx.x;   // B*2*16384 = 131072
    const int bw = e >> 14, loc = e & 16383;
    float sum = 0.f;
#pragma unroll
    for (int s = 0; s < SPLIT; s++)
        sum += g_part[(size_t)(bw * SPLIT + s) * (ICDIM * ICDIM) + loc];
    g_Ms[(size_t)bw * (ICDIM * ICDIM) + loc] = sum * (1.0f / 4096.0f);
}

// ---------------------------------------------------------------------------
// Combine: dst[(q*16+p), c0+c] = sum_i M[i,q] * src[(i*16+p), c0+c]
// A-side (M) and B-side (src) are both k-major -> direct float4 smem fills.
// grid (2 c-tiles, 16 p, B*2), 256 threads, double-buffered.
// ---------------------------------------------------------------------------
__global__ __launch_bounds__(256) void combine_k()
{
    const int ct = blockIdx.x;
    const int p  = blockIdx.y;
    const int bw = blockIdx.z;
    const int b = bw >> 1, which = bw & 1;
    const float* __restrict__ src = (which ? g_Xphi : g_Xtheta) + (size_t)b * PER_B;
    const float* __restrict__ M   = g_Ms + (size_t)bw * (ICDIM * ICDIM);
    float* __restrict__ dst = (which ? g_Tdet : g_Taim) + (size_t)b * PER_B;
    const int c0 = ct * 128;

    __shared__ float As[2][8][128];   // As[k][q]
    __shared__ float Bs[2][8][128];   // Bs[k][c]
    const int t = threadIdx.x;
    const int ty = (t >> 4), tx = (t & 15);
    const int kq = t >> 5;            // 0..7
    const int q4 = (t & 31) * 4;      // 0..124

    float acc[8][8];
#pragma unroll
    for (int i = 0; i < 8; i++)
#pragma unroll
        for (int j = 0; j < 8; j++) acc[i][j] = 0.f;

    const float* Ap = M + (size_t)kq * ICDIM + q4;                   // +8*128/iter
    const float* Bp = src + ((size_t)kq * 16 + p) * CDIM + c0 + q4;  // +8*16*256/iter

    {
        *(float4*)&As[0][kq][q4] = *(const float4*)Ap;
        *(float4*)&Bs[0][kq][q4] = *(const float4*)Bp;
    }
    __syncthreads();

    const int nIter = ICDIM / 8;  // 16
    for (int it = 0; it < nIter; ++it) {
        const int cur = it & 1, nxt = cur ^ 1;
        const bool has = (it + 1 < nIter);
        float4 av2, bv2;
        if (has) {
            av2 = *(const float4*)(Ap + (size_t)(it + 1) * 8 * ICDIM);
            bv2 = *(const float4*)(Bp + (size_t)(it + 1) * 8 * 16 * CDIM);
        }
#pragma unroll
        for (int kk = 0; kk < 8; kk++) {
            float a[8], x[8];
            *(float4*)&a[0] = *(const float4*)&As[cur][kk][ty*4];
            *(float4*)&a[4] = *(const float4*)&As[cur][kk][64 + ty*4];
            *(float4*)&x[0] = *(const float4*)&Bs[cur][kk][tx*4];
            *(float4*)&x[4] = *(const float4*)&Bs[cur][kk][64 + tx*4];
#pragma unroll
            for (int i = 0; i < 8; i++)
#pragma unroll
                for (int j = 0; j < 8; j++)
                    acc[i][j] = fmaf(a[i], x[j], acc[i][j]);
        }
        if (has) {
            *(float4*)&As[nxt][kq][q4] = av2;
            *(float4*)&Bs[nxt][kq][q4] = bv2;
            __syncthreads();
        }
    }

#pragma unroll
    for (int i = 0; i < 8; i++) {
        const int q = (i < 4) ? (ty*4 + i) : (64 + ty*4 + i - 4);
        *(float4*)(dst + (size_t)(q * 16 + p) * CDIM + c0 + tx*4)      = *(float4*)&acc[i][0];
        *(float4*)(dst + (size_t)(q * 16 + p) * CDIM + c0 + 64 + tx*4) = *(float4*)&acc[i][4];
    }
}

// ---------------------------------------------------------------------------
extern "C" void kernel_launch(void* const* d_in, const int* in_sizes, int n_in,
                              void* d_out, int out_size)
{
    const float* detect  = (const float*)d_in[0];
    const float* aim     = (const float*)d_in[1];
    const float* g_w     = (const float*)d_in[2];
    const float* g_b     = (const float*)d_in[3];
    const float* g2_w    = (const float*)d_in[4];
    const float* g2_b    = (const float*)d_in[5];
    const float* theta_w = (const float*)d_in[6];
    const float* theta_b = (const float*)d_in[7];
    const float* phi_w   = (const float*)d_in[8];
    const float* phi_b   = (const float*)d_in[9];
    const float* W_w     = (const float*)d_in[10];
    const float* W_b     = (const float*)d_in[11];
    const float* Q_w     = (const float*)d_in[12];
    const float* Q_b     = (const float*)d_in[13];

    dim3 blk(256);

    proj_k<<<dim3(MTOT/128, CDIM/128, 4), blk>>>(
        detect, aim, g_w, g_b, phi_w, phi_b, g2_w, g2_b, theta_w, theta_b);

    pairdot_k<<<dim3(SPLIT, 2, BBATCH), blk>>>();
    reduce_k<<<dim3(BBATCH * 2 * ICDIM * ICDIM / 256), blk>>>();

    combine_k<<<dim3(2, 16, BBATCH * 2), blk>>>();

    outlin_k<<<dim3(MTOT/128, CDIM/128, 2), blk>>>(
        Q_w, Q_b, W_w, W_b, detect, aim, (float*)d_out);
}

// round 11
// speedup vs baseline: 2.4041x; 1.5477x over previous
#include <cuda_runtime.h>
#include <cuda_bf16.h>
#include <cstdint>

// Problem constants
#define BBATCH 4
#define NROW   2048
#define CDIM   256
#define ICDIM  128
#define MTOT   (BBATCH*NROW)       // 8192
#define PER_B  (NROW*CDIM)         // 524288
#define TWO_N  4096
#define SPLIT  32
#define KCH    (TWO_N/SPLIT)       // 128

// ---------------- scratch (static device globals) ----------------
__device__ __nv_bfloat16 g_dhi[MTOT*CDIM], g_dlo[MTOT*CDIM];
__device__ __nv_bfloat16 g_ahi[MTOT*CDIM], g_alo[MTOT*CDIM];
__device__ __nv_bfloat16 g_whi[6*CDIM*CDIM], g_wlo[6*CDIM*CDIM]; // 0=g,1=phi,2=g2,3=theta,4=W,5=Q

__device__ __nv_bfloat16 g_Xg_hi[MTOT*CDIM],  g_Xg_lo[MTOT*CDIM];
__device__ __nv_bfloat16 g_Xphi_hi[MTOT*CDIM],g_Xphi_lo[MTOT*CDIM];
__device__ __nv_bfloat16 g_Xg2_hi[MTOT*CDIM], g_Xg2_lo[MTOT*CDIM];
__device__ __nv_bfloat16 g_Xth_hi[MTOT*CDIM], g_Xth_lo[MTOT*CDIM];
__device__ float g_Xphi_f[MTOT*CDIM];
__device__ float g_Xth_f[MTOT*CDIM];

__device__ float g_part[BBATCH*2*SPLIT*ICDIM*ICDIM];
__device__ float g_Ms[BBATCH*2*ICDIM*ICDIM];

__device__ __nv_bfloat16 g_Td_hi[MTOT*CDIM], g_Td_lo[MTOT*CDIM];
__device__ __nv_bfloat16 g_Ta_hi[MTOT*CDIM], g_Ta_lo[MTOT*CDIM];

// ---------------- helpers ----------------
__device__ __forceinline__ uint32_t smem_to_u32(const void* p) {
    uint32_t a;
    asm("{ .reg .u64 t; cvta.to.shared.u64 t, %1; cvt.u32.u64 %0, t; }" : "=r"(a) : "l"(p));
    return a;
}
// swizzled byte offset inside a 128x32 bf16 tile (64B rows, 4x16B segs)
__device__ __forceinline__ uint32_t lds_off(int row, int seg) {
    return (uint32_t)(row * 64 + ((seg ^ ((row >> 1) & 3)) << 4));
}
__device__ __forceinline__ void ldm_x4(uint32_t* r, uint32_t addr) {
    asm volatile("ldmatrix.sync.aligned.m8n8.x4.shared.b16 {%0,%1,%2,%3}, [%4];"
        : "=r"(r[0]), "=r"(r[1]), "=r"(r[2]), "=r"(r[3]) : "r"(addr));
}
__device__ __forceinline__ void mma16816(float* d, const uint32_t* a, const uint32_t* b) {
    asm volatile(
        "mma.sync.aligned.m16n8k16.row.col.f32.bf16.bf16.f32 "
        "{%0,%1,%2,%3}, {%4,%5,%6,%7}, {%8,%9}, {%0,%1,%2,%3};"
        : "+f"(d[0]), "+f"(d[1]), "+f"(d[2]), "+f"(d[3])
        : "r"(a[0]), "r"(a[1]), "r"(a[2]), "r"(a[3]), "r"(b[0]), "r"(b[1]));
}

__device__ __forceinline__ void split1(float v, __nv_bfloat16& h, __nv_bfloat16& l) {
    h = __float2bfloat16(v);
    l = __float2bfloat16(v - __bfloat162float(h));
}
__device__ __forceinline__ uint32_t pk2(__nv_bfloat16 a, __nv_bfloat16 b) {
    __nv_bfloat162 t; t.x = a; t.y = b;
    return *reinterpret_cast<uint32_t*>(&t);
}
__device__ __forceinline__ void store4_hl(__nv_bfloat16* hi, __nv_bfloat16* lo,
                                          size_t off, const float* v) {
    __nv_bfloat16 h[4], l[4];
#pragma unroll
    for (int j = 0; j < 4; j++) split1(v[j], h[j], l[j]);
    uint2 uh; uh.x = pk2(h[0], h[1]); uh.y = pk2(h[2], h[3]);
    uint2 ul; ul.x = pk2(l[0], l[1]); ul.y = pk2(l[2], l[3]);
    *(uint2*)(hi + off) = uh;
    *(uint2*)(lo + off) = ul;
}
__device__ __forceinline__ void store2_hl(__nv_bfloat16* hi, __nv_bfloat16* lo,
                                          size_t off, float v0, float v1) {
    __nv_bfloat16 h0, l0, h1, l1;
    split1(v0, h0, l0); split1(v1, h1, l1);
    *(uint32_t*)(hi + off) = pk2(h0, h1);
    *(uint32_t*)(lo + off) = pk2(l0, l1);
}

// ---------------------------------------------------------------------------
// Core: 128x128 NT-GEMM via bf16 HMMA, hi/lo 3-pass. BK=32, single-buffered.
// 8 warps as 2x4; warp tile 64x32. Both A and B are K-contiguous -> both use
// NON-trans ldmatrix (fragment k-pairs are contiguous in storage).
// ---------------------------------------------------------------------------
__device__ __forceinline__ void mma_core(
    const __nv_bfloat16* __restrict__ Ahi, const __nv_bfloat16* __restrict__ Alo,
    const __nv_bfloat16* __restrict__ Bhi, const __nv_bfloat16* __restrict__ Blo,
    int sA, int sB, int nChunks,
    char* shAhi, char* shAlo, char* shBhi, char* shBlo,
    float (&acc)[4][4][4])
{
    const int t = threadIdx.x;
    const int lane = t & 31, wid = t >> 5;
    const int wm = wid >> 2, wn = wid & 3;
    const uint32_t uAhi = smem_to_u32(shAhi), uAlo = smem_to_u32(shAlo);
    const uint32_t uBhi = smem_to_u32(shBhi), uBlo = smem_to_u32(shBlo);

    const int arow = wm * 64 + (lane & 15);                     // + mi*16
    const int akh  = lane >> 4;                                 // k-half
    const int brow = wn * 32 + (lane & 7) + ((lane & 16) >> 1); // + nt*16
    const int bkh  = (lane >> 3) & 1;

    const int lrow = t >> 2, lseg = t & 3;   // gmem->smem fill mapping
    const uint32_t off0 = lds_off(lrow, lseg);
    const uint32_t off1 = lds_off(lrow + 64, lseg);

    for (int ch = 0; ch < nChunks; ++ch) {
        __syncthreads();
        {
            size_t ga0 = (size_t)lrow * sA + ch * 32 + lseg * 8;
            size_t ga1 = (size_t)(lrow + 64) * sA + ch * 32 + lseg * 8;
            size_t gb0 = (size_t)lrow * sB + ch * 32 + lseg * 8;
            size_t gb1 = (size_t)(lrow + 64) * sB + ch * 32 + lseg * 8;
            *(uint4*)(shAhi + off0) = *(const uint4*)(Ahi + ga0);
            *(uint4*)(shAhi + off1) = *(const uint4*)(Ahi + ga1);
            *(uint4*)(shAlo + off0) = *(const uint4*)(Alo + ga0);
            *(uint4*)(shAlo + off1) = *(const uint4*)(Alo + ga1);
            *(uint4*)(shBhi + off0) = *(const uint4*)(Bhi + gb0);
            *(uint4*)(shBhi + off1) = *(const uint4*)(Bhi + gb1);
            *(uint4*)(shBlo + off0) = *(const uint4*)(Blo + gb0);
            *(uint4*)(shBlo + off1) = *(const uint4*)(Blo + gb1);
        }
        __syncthreads();

#pragma unroll
        for (int kk = 0; kk < 2; ++kk) {
            const int aseg = (kk << 1) | akh;
            const int bseg = (kk << 1) | bkh;
            uint32_t a[4][4], b[2][4];

            // pass 0: Ahi x Bhi
#pragma unroll
            for (int mi = 0; mi < 4; ++mi)
                ldm_x4(a[mi], uAhi + lds_off(arow + mi * 16, aseg));
#pragma unroll
            for (int nt = 0; nt < 2; ++nt)
                ldm_x4(b[nt], uBhi + lds_off(brow + nt * 16, bseg));
#pragma unroll
            for (int mi = 0; mi < 4; ++mi)
#pragma unroll
                for (int ni = 0; ni < 4; ++ni)
                    mma16816(acc[mi][ni], a[mi], &b[ni >> 1][(ni & 1) * 2]);

            // pass 1: Ahi x Blo
#pragma unroll
            for (int nt = 0; nt < 2; ++nt)
                ldm_x4(b[nt], uBlo + lds_off(brow + nt * 16, bseg));
#pragma unroll
            for (int mi = 0; mi < 4; ++mi)
#pragma unroll
                for (int ni = 0; ni < 4; ++ni)
                    mma16816(acc[mi][ni], a[mi], &b[ni >> 1][(ni & 1) * 2]);

            // pass 2: Alo x Bhi
#pragma unroll
            for (int mi = 0; mi < 4; ++mi)
                ldm_x4(a[mi], uAlo + lds_off(arow + mi * 16, aseg));
#pragma unroll
            for (int nt = 0; nt < 2; ++nt)
                ldm_x4(b[nt], uBhi + lds_off(brow + nt * 16, bseg));
#pragma unroll
            for (int mi = 0; mi < 4; ++mi)
#pragma unroll
                for (int ni = 0; ni < 4; ++ni)
                    mma16816(acc[mi][ni], a[mi], &b[ni >> 1][(ni & 1) * 2]);
        }
    }
}

// ---------------- prep: split fp32 -> bf16 hi/lo ----------------
__global__ void prep_big_k(const float* __restrict__ detect, const float* __restrict__ aim)
{
    const int z = blockIdx.z;
    const float* src = z ? aim : detect;
    __nv_bfloat16* hi = z ? g_ahi : g_dhi;
    __nv_bfloat16* lo = z ? g_alo : g_dlo;
    size_t i = ((size_t)blockIdx.x * 256 + threadIdx.x) * 4;
    float4 v = *(const float4*)(src + i);
    float vv[4] = {v.x, v.y, v.z, v.w};
    store4_hl(hi, lo, i, vv);
}
__global__ void prep_w_k(const float* __restrict__ w0, const float* __restrict__ w1,
                         const float* __restrict__ w2, const float* __restrict__ w3,
                         const float* __restrict__ w4, const float* __restrict__ w5)
{
    const int z = blockIdx.z;
    const float* src = (z==0)?w0:(z==1)?w1:(z==2)?w2:(z==3)?w3:(z==4)?w4:w5;
    __nv_bfloat16* hi = g_whi + (size_t)z * CDIM * CDIM;
    __nv_bfloat16* lo = g_wlo + (size_t)z * CDIM * CDIM;
    size_t i = ((size_t)blockIdx.x * 256 + threadIdx.x) * 4;
    float4 v = *(const float4*)(src + i);
    float vv[4] = {v.x, v.y, v.z, v.w};
    store4_hl(hi, lo, i, vv);
}

// ---------------- projection linears (HMMA) ----------------
// grid (64, 2, 4)
__global__ __launch_bounds__(256, 2) void proj_mma(
    const float* __restrict__ g_b, const float* __restrict__ phi_b,
    const float* __restrict__ g2_b, const float* __restrict__ theta_b)
{
    __shared__ __align__(16) char shAhi[8192], shAlo[8192], shBhi[8192], shBlo[8192];
    __shared__ float sbias[128];
    const int t = threadIdx.x;
    const int z = blockIdx.z;
    const int m0 = blockIdx.x * 128, n0 = blockIdx.y * 128;

    const __nv_bfloat16 *Xhi, *Xlo;
    if (z < 2) { Xhi = g_dhi; Xlo = g_dlo; } else { Xhi = g_ahi; Xlo = g_alo; }
    const __nv_bfloat16* Whi = g_whi + (size_t)z * CDIM * CDIM;
    const __nv_bfloat16* Wlo = g_wlo + (size_t)z * CDIM * CDIM;
    const float* bias = (z==0)?g_b:(z==1)?phi_b:(z==2)?g2_b:theta_b;
    __nv_bfloat16* Yhi = (z==0)?g_Xg_hi:(z==1)?g_Xphi_hi:(z==2)?g_Xg2_hi:g_Xth_hi;
    __nv_bfloat16* Ylo = (z==0)?g_Xg_lo:(z==1)?g_Xphi_lo:(z==2)?g_Xg2_lo:g_Xth_lo;
    float* Yf = (z==1)?g_Xphi_f:(z==3)?g_Xth_f:(float*)0;

    if (t < 128) sbias[t] = bias[n0 + t];

    float acc[4][4][4];
#pragma unroll
    for (int i = 0; i < 4; i++)
#pragma unroll
        for (int j = 0; j < 4; j++)
#pragma unroll
            for (int r = 0; r < 4; r++) acc[i][j][r] = 0.f;

    mma_core(Xhi + (size_t)m0 * CDIM, Xlo + (size_t)m0 * CDIM,
             Whi + (size_t)n0 * CDIM, Wlo + (size_t)n0 * CDIM,
             CDIM, CDIM, CDIM / 32, shAhi, shAlo, shBhi, shBlo, acc);

    const int lane = t & 31, wid = t >> 5;
    const int wm = wid >> 2, wn = wid & 3;
    const int lr = lane >> 2, lc = lane & 3;
#pragma unroll
    for (int mi = 0; mi < 4; ++mi)
#pragma unroll
        for (int ni = 0; ni < 4; ++ni) {
            const int ml = wm * 64 + mi * 16 + lr;
            const int nl = wn * 32 + ni * 8 + lc * 2;
            float v0 = acc[mi][ni][0] + sbias[nl];
            float v1 = acc[mi][ni][1] + sbias[nl + 1];
            float v2 = acc[mi][ni][2] + sbias[nl];
            float v3 = acc[mi][ni][3] + sbias[nl + 1];
            size_t o0 = (size_t)(m0 + ml) * CDIM + n0 + nl;
            size_t o1 = (size_t)(m0 + ml + 8) * CDIM + n0 + nl;
            store2_hl(Yhi, Ylo, o0, v0, v1);
            store2_hl(Yhi, Ylo, o1, v2, v3);
            if (Yf) {
                float2 f0; f0.x = v0; f0.y = v1;
                float2 f1; f1.x = v2; f1.y = v3;
                *(float2*)(Yf + o0) = f0;
                *(float2*)(Yf + o1) = f1;
            }
        }
}

// ---------------- pairdot (HMMA, split-K) ----------------
// grid (SPLIT, 2, B)
__global__ __launch_bounds__(256, 2) void pairdot_mma()
{
    __shared__ __align__(16) char shAhi[8192], shAlo[8192], shBhi[8192], shBlo[8192];
    const int t = threadIdx.x;
    const int s = blockIdx.x, which = blockIdx.y, b = blockIdx.z;

    const __nv_bfloat16* Ahi = (which ? g_Xth_hi : g_Xphi_hi) + (size_t)b * PER_B;
    const __nv_bfloat16* Alo = (which ? g_Xth_lo : g_Xphi_lo) + (size_t)b * PER_B;
    const __nv_bfloat16* Bhi = (which ? g_Xg2_hi : g_Xg_hi) + (size_t)b * PER_B;
    const __nv_bfloat16* Blo = (which ? g_Xg2_lo : g_Xg_lo) + (size_t)b * PER_B;
    float* out = g_part + (size_t)((b * 2 + which) * SPLIT + s) * (ICDIM * ICDIM);

    float acc[4][4][4];
#pragma unroll
    for (int i = 0; i < 4; i++)
#pragma unroll
        for (int j = 0; j < 4; j++)
#pragma unroll
            for (int r = 0; r < 4; r++) acc[i][j][r] = 0.f;

    const int kbeg = s * KCH;
    mma_core(Ahi + kbeg, Alo + kbeg, Bhi + kbeg, Blo + kbeg,
             TWO_N, TWO_N, KCH / 32, shAhi, shAlo, shBhi, shBlo, acc);

    const int lane = t & 31, wid = t >> 5;
    const int wm = wid >> 2, wn = wid & 3;
    const int lr = lane >> 2, lc = lane & 3;
#pragma unroll
    for (int mi = 0; mi < 4; ++mi)
#pragma unroll
        for (int ni = 0; ni < 4; ++ni) {
            const int ml = wm * 64 + mi * 16 + lr;
            const int nl = wn * 32 + ni * 8 + lc * 2;
            float2 f0; f0.x = acc[mi][ni][0]; f0.y = acc[mi][ni][1];
            float2 f1; f1.x = acc[mi][ni][2]; f1.y = acc[mi][ni][3];
            *(float2*)(out + (size_t)ml * ICDIM + nl)       = f0;
            *(float2*)(out + (size_t)(ml + 8) * ICDIM + nl) = f1;
        }
}

// ---------------- split-K reduce (f32) ----------------
__global__ void reduce_k()
{
    const int e = blockIdx.x * 256 + threadIdx.x;   // 131072
    const int bw = e >> 14, loc = e & 16383;
    float sum = 0.f;
#pragma unroll
    for (int s = 0; s < SPLIT; s++)
        sum += g_part[(size_t)(bw * SPLIT + s) * (ICDIM * ICDIM) + loc];
    g_Ms[(size_t)bw * (ICDIM * ICDIM) + loc] = sum * (1.0f / 4096.0f);
}

// ---------------- combine (FFMA, f32 in, bf16 hi/lo out) ----------------
__global__ __launch_bounds__(256) void combine_k()
{
    const int ct = blockIdx.x;
    const int p  = blockIdx.y;
    const int bw = blockIdx.z;
    const int b = bw >> 1, which = bw & 1;
    const float* __restrict__ src = (which ? g_Xphi_f : g_Xth_f) + (size_t)b * PER_B;
    const float* __restrict__ M   = g_Ms + (size_t)bw * (ICDIM * ICDIM);
    __nv_bfloat16* dhi = (which ? g_Td_hi : g_Ta_hi) + (size_t)b * PER_B;
    __nv_bfloat16* dlo = (which ? g_Td_lo : g_Ta_lo) + (size_t)b * PER_B;
    const int c0 = ct * 128;

    __shared__ float As[2][8][128];
    __shared__ float Bs[2][8][128];
    const int t = threadIdx.x;
    const int ty = (t >> 4), tx = (t & 15);
    const int kq = t >> 5;
    const int q4 = (t & 31) * 4;

    float acc[8][8];
#pragma unroll
    for (int i = 0; i < 8; i++)
#pragma unroll
        for (int j = 0; j < 8; j++) acc[i][j] = 0.f;

    const float* Ap = M + (size_t)kq * ICDIM + q4;
    const float* Bp = src + ((size_t)kq * 16 + p) * CDIM + c0 + q4;

    *(float4*)&As[0][kq][q4] = *(const float4*)Ap;
    *(float4*)&Bs[0][kq][q4] = *(const float4*)Bp;
    __syncthreads();

    const int nIter = ICDIM / 8;
    for (int it = 0; it < nIter; ++it) {
        const int cur = it & 1, nxt = cur ^ 1;
        const bool has = (it + 1 < nIter);
        float4 av2, bv2;
        if (has) {
            av2 = *(const float4*)(Ap + (size_t)(it + 1) * 8 * ICDIM);
            bv2 = *(const float4*)(Bp + (size_t)(it + 1) * 8 * 16 * CDIM);
        }
#pragma unroll
        for (int kk = 0; kk < 8; kk++) {
            float a[8], x[8];
            *(float4*)&a[0] = *(const float4*)&As[cur][kk][ty*4];
            *(float4*)&a[4] = *(const float4*)&As[cur][kk][64 + ty*4];
            *(float4*)&x[0] = *(const float4*)&Bs[cur][kk][tx*4];
            *(float4*)&x[4] = *(const float4*)&Bs[cur][kk][64 + tx*4];
#pragma unroll
            for (int i = 0; i < 8; i++)
#pragma unroll
                for (int j = 0; j < 8; j++)
                    acc[i][j] = fmaf(a[i], x[j], acc[i][j]);
        }
        if (has) {
            *(float4*)&As[nxt][kq][q4] = av2;
            *(float4*)&Bs[nxt][kq][q4] = bv2;
            __syncthreads();
        }
    }

#pragma unroll
    for (int i = 0; i < 8; i++) {
        const int q = (i < 4) ? (ty*4 + i) : (64 + ty*4 + i - 4);
        size_t base = (size_t)(q * 16 + p) * CDIM + c0;
        store4_hl(dhi, dlo, base + tx*4,      &acc[i][0]);
        store4_hl(dhi, dlo, base + 64 + tx*4, &acc[i][4]);
    }
}

// ---------------- output linears (HMMA) + bias + residual ----------------
// grid (64, 2, 2)
__global__ __launch_bounds__(256, 2) void outlin_mma(
    const float* __restrict__ Q_b, const float* __restrict__ W_b,
    const float* __restrict__ detect, const float* __restrict__ aim,
    float* __restrict__ out)
{
    __shared__ __align__(16) char shAhi[8192], shAlo[8192], shBhi[8192], shBlo[8192];
    __shared__ float sbias[128];
    const int t = threadIdx.x;
    const int z = blockIdx.z;
    const int m0 = blockIdx.x * 128, n0 = blockIdx.y * 128;

    const __nv_bfloat16* Xhi = z ? g_Ta_hi : g_Td_hi;
    const __nv_bfloat16* Xlo = z ? g_Ta_lo : g_Td_lo;
    const int widx = z ? 4 : 5;   // W : Q
    const __nv_bfloat16* Whi = g_whi + (size_t)widx * CDIM * CDIM;
    const __nv_bfloat16* Wlo = g_wlo + (size_t)widx * CDIM * CDIM;
    const float* bias = z ? W_b : Q_b;
    const float* res  = z ? aim : detect;
    float* Y = out + (size_t)z * MTOT * CDIM;

    if (t < 128) sbias[t] = bias[n0 + t];

    float acc[4][4][4];
#pragma unroll
    for (int i = 0; i < 4; i++)
#pragma unroll
        for (int j = 0; j < 4; j++)
#pragma unroll
            for (int r = 0; r < 4; r++) acc[i][j][r] = 0.f;

    mma_core(Xhi + (size_t)m0 * CDIM, Xlo + (size_t)m0 * CDIM,
             Whi + (size_t)n0 * CDIM, Wlo + (size_t)n0 * CDIM,
             CDIM, CDIM, CDIM / 32, shAhi, shAlo, shBhi, shBlo, acc);

    const int lane = t & 31, wid = t >> 5;
    const int wm = wid >> 2, wn = wid & 3;
    const int lr = lane >> 2, lc = lane & 3;
#pragma unroll
    for (int mi = 0; mi < 4; ++mi)
#pragma unroll
        for (int ni = 0; ni < 4; ++ni) {
            const int ml = wm * 64 + mi * 16 + lr;
            const int nl = wn * 32 + ni * 8 + lc * 2;
            size_t o0 = (size_t)(m0 + ml) * CDIM + n0 + nl;
            size_t o1 = (size_t)(m0 + ml + 8) * CDIM + n0 + nl;
            float2 r0 = *(const float2*)(res + o0);
            float2 r1 = *(const float2*)(res + o1);
            float2 v0, v1;
            v0.x = acc[mi][ni][0] + sbias[nl]     + r0.x;
            v0.y = acc[mi][ni][1] + sbias[nl + 1] + r0.y;
            v1.x = acc[mi][ni][2] + sbias[nl]     + r1.x;
            v1.y = acc[mi][ni][3] + sbias[nl + 1] + r1.y;
            *(float2*)(Y + o0) = v0;
            *(float2*)(Y + o1) = v1;
        }
}

// ---------------------------------------------------------------------------
extern "C" void kernel_launch(void* const* d_in, const int* in_sizes, int n_in,
                              void* d_out, int out_size)
{
    const float* detect  = (const float*)d_in[0];
    const float* aim     = (const float*)d_in[1];
    const float* g_w     = (const float*)d_in[2];
    const float* g_b     = (const float*)d_in[3];
    const float* g2_w    = (const float*)d_in[4];
    const float* g2_b    = (const float*)d_in[5];
    const float* theta_w = (const float*)d_in[6];
    const float* theta_b = (const float*)d_in[7];
    const float* phi_w   = (const float*)d_in[8];
    const float* phi_b   = (const float*)d_in[9];
    const float* W_w     = (const float*)d_in[10];
    const float* W_b     = (const float*)d_in[11];
    const float* Q_w     = (const float*)d_in[12];
    const float* Q_b     = (const float*)d_in[13];

    dim3 blk(256);

    // Stage 0: hi/lo splits
    prep_big_k<<<dim3(MTOT*CDIM/1024, 1, 2), blk>>>(detect, aim);
    prep_w_k<<<dim3(CDIM*CDIM/1024, 1, 6), blk>>>(g_w, phi_w, g2_w, theta_w, W_w, Q_w);

    // Stage 1: projections (HMMA)
    proj_mma<<<dim3(MTOT/128, CDIM/128, 4), blk>>>(g_b, phi_b, g2_b, theta_b);

    // Stage 2: 128x128 inner matrices (HMMA split-K) + reduce
    pairdot_mma<<<dim3(SPLIT, 2, BBATCH), blk>>>();
    reduce_k<<<dim3(BBATCH * 2 * ICDIM * ICDIM / 256), blk>>>();

    // Stage 3: combine (FFMA)
    combine_k<<<dim3(2, 16, BBATCH * 2), blk>>>();

    // Stage 4: output linears (HMMA) + bias + residual
    outlin_mma<<<dim3(MTOT/128, CDIM/128, 2), blk>>>(Q_b, W_b, detect, aim, (float*)d_out);
}